// round 1
// baseline (speedup 1.0000x reference)
#include <cuda_runtime.h>
#include <cuda_bf16.h>

#define TSEQ 4096
#define DHEAD 64
#define BS 128
#define NB 32
#define NH 16
#define NBH 32

// ---------------------------------------------------------------------------
// Kernel 1: block-local attention. One CTA per (bh, block).
// 256 threads: 2 threads per query row, each owns 32 of 64 dims.
// Online softmax over [global token] + 6x64-key window chunks.
// ---------------------------------------------------------------------------
__global__ __launch_bounds__(256)
void attn_block_kernel(const float* __restrict__ Q, const float* __restrict__ K,
                       const float* __restrict__ V, const float* __restrict__ M,
                       float* __restrict__ O) {
    const int b   = blockIdx.x;    // query block 0..31
    const int bh  = blockIdx.y;    // batch*head 0..31
    const int nIdx = bh / NH;
    const int tid  = threadIdx.x;
    const int row  = tid >> 1;     // 0..127
    const int half = tid & 1;      // 0 or 1 (dims half*32 .. half*32+31)
    const float scale = 0.125f;    // 1/sqrt(64)

    const float* Qb   = Q + ((size_t)bh * TSEQ + (size_t)b * BS) * DHEAD;
    const float* Kb   = K + (size_t)bh * TSEQ * DHEAD;
    const float* Vb   = V + (size_t)bh * TSEQ * DHEAD;
    const float* Mrow = M + (size_t)nIdx * TSEQ;

    __shared__ float Ksh[64][64];
    __shared__ float Vsh[64][64];
    __shared__ float Msh[64];

    // Load this thread's half of its query row into registers.
    float q[32];
    {
        const float4* qp = (const float4*)(Qb + row * DHEAD + half * 32);
        #pragma unroll
        for (int i = 0; i < 8; i++) {
            float4 t = qp[i];
            q[4*i+0] = t.x; q[4*i+1] = t.y; q[4*i+2] = t.z; q[4*i+3] = t.w;
        }
    }

    // Seed online softmax with the global token (k[0], v[0], mask = 0).
    float acc[32];
    float m, l;
    {
        float partial = 0.f;
        #pragma unroll
        for (int i = 0; i < 32; i++) partial += q[i] * __ldg(Kb + half * 32 + i);
        float s0 = (partial + __shfl_xor_sync(0xffffffffu, partial, 1)) * scale;
        m = s0; l = 1.f;
        #pragma unroll
        for (int i = 0; i < 32; i++) acc[i] = __ldg(Vb + half * 32 + i);
    }

    // Window: blocks b-1, b, b+1 -> six 64-key chunks, skip fully-OOB chunks.
    for (int sc = 0; sc < 6; sc++) {
        const int kb0 = (b - 1) * BS + sc * 64;    // uniform across CTA
        if (kb0 < 0 || kb0 >= TSEQ) continue;

        __syncthreads();   // protect previous chunk's smem reads
        {
            const float4* ksrc = (const float4*)(Kb + (size_t)kb0 * DHEAD);
            const float4* vsrc = (const float4*)(Vb + (size_t)kb0 * DHEAD);
            float4* kdst = (float4*)&Ksh[0][0];
            float4* vdst = (float4*)&Vsh[0][0];
            #pragma unroll
            for (int i = tid; i < 64 * 64 / 4; i += 256) {
                kdst[i] = ksrc[i];
                vdst[i] = vsrc[i];
            }
            if (tid < 16) ((float4*)Msh)[tid] = ((const float4*)(Mrow + kb0))[tid];
        }
        __syncthreads();

        // 4 groups of 16 keys: stage scores, then one rescale per group.
        for (int g = 0; g < 4; g++) {
            float s[16];
            #pragma unroll
            for (int j = 0; j < 16; j++) {
                const int jj = g * 16 + j;
                float partial = 0.f;
                const float4* kp = (const float4*)&Ksh[jj][half * 32];
                #pragma unroll
                for (int i = 0; i < 8; i++) {
                    float4 kv = kp[i];
                    partial += q[4*i+0]*kv.x + q[4*i+1]*kv.y
                             + q[4*i+2]*kv.z + q[4*i+3]*kv.w;
                }
                float full = partial + __shfl_xor_sync(0xffffffffu, partial, 1);
                float sv = full * scale + Msh[jj];
                if (kb0 + jj == 0) sv = -1e30f;   // window never sees position 0
                s[j] = sv;
            }
            float mloc = s[0];
            #pragma unroll
            for (int j = 1; j < 16; j++) mloc = fmaxf(mloc, s[j]);
            float mnew = fmaxf(m, mloc);
            float corr = __expf(m - mnew);
            l *= corr;
            #pragma unroll
            for (int i = 0; i < 32; i++) acc[i] *= corr;
            #pragma unroll
            for (int j = 0; j < 16; j++) {
                float e = __expf(s[j] - mnew);
                l += e;
                const float4* vp = (const float4*)&Vsh[g * 16 + j][half * 32];
                #pragma unroll
                for (int i = 0; i < 8; i++) {
                    float4 vv = vp[i];
                    acc[4*i+0] += e * vv.x; acc[4*i+1] += e * vv.y;
                    acc[4*i+2] += e * vv.z; acc[4*i+3] += e * vv.w;
                }
            }
            m = mnew;
        }
    }

    // Epilogue: normalize and store.
    const float inv = 1.f / l;
    float4* op = (float4*)(O + ((size_t)bh * TSEQ + (size_t)b * BS + row) * DHEAD
                             + half * 32);
    #pragma unroll
    for (int i = 0; i < 8; i++) {
        op[i] = make_float4(acc[4*i+0] * inv, acc[4*i+1] * inv,
                            acc[4*i+2] * inv, acc[4*i+3] * inv);
    }
}

// ---------------------------------------------------------------------------
// Kernel 2: global query row (t=0) does full attention over all 4096 keys,
// overwriting row 0 of each bh. One CTA per bh. Must run after kernel 1.
// ---------------------------------------------------------------------------
__global__ __launch_bounds__(256)
void attn_global_kernel(const float* __restrict__ Q, const float* __restrict__ K,
                        const float* __restrict__ V, const float* __restrict__ M,
                        float* __restrict__ O) {
    const int bh   = blockIdx.x;
    const int nIdx = bh / NH;
    const int tid  = threadIdx.x;

    __shared__ float sc[TSEQ];     // 16 KB scores -> exp weights
    __shared__ float q0[DHEAD];
    __shared__ float red[256];
    __shared__ float part[4][DHEAD];

    const float* Qr   = Q + (size_t)bh * TSEQ * DHEAD;
    const float* Kb   = K + (size_t)bh * TSEQ * DHEAD;
    const float* Vb   = V + (size_t)bh * TSEQ * DHEAD;
    const float* Mrow = M + (size_t)nIdx * TSEQ;

    if (tid < DHEAD) q0[tid] = Qr[tid];
    __syncthreads();

    // Pass 1: scores + local max.
    float lmax = -1e30f;
    for (int j = tid; j < TSEQ; j += 256) {
        float dot = 0.f;
        const float4* kp = (const float4*)(Kb + (size_t)j * DHEAD);
        #pragma unroll
        for (int i = 0; i < 16; i++) {
            float4 kv = kp[i];
            dot += q0[4*i+0]*kv.x + q0[4*i+1]*kv.y
                 + q0[4*i+2]*kv.z + q0[4*i+3]*kv.w;
        }
        float s = dot * 0.125f + Mrow[j];
        sc[j] = s;
        lmax = fmaxf(lmax, s);
    }
    red[tid] = lmax; __syncthreads();
    for (int st = 128; st > 0; st >>= 1) {
        if (tid < st) red[tid] = fmaxf(red[tid], red[tid + st]);
        __syncthreads();
    }
    const float mblk = red[0];
    __syncthreads();

    // Pass 2: exponentiate + sum.
    float lsum = 0.f;
    for (int j = tid; j < TSEQ; j += 256) {
        float e = __expf(sc[j] - mblk);
        sc[j] = e;
        lsum += e;
    }
    red[tid] = lsum; __syncthreads();
    for (int st = 128; st > 0; st >>= 1) {
        if (tid < st) red[tid] += red[tid + st];
        __syncthreads();
    }
    const float L = red[0];
    __syncthreads();

    // Pass 3: weighted V sum. 64 dims x 4 key-stripes.
    const int dm = tid & 63;
    const int st = tid >> 6;
    float a0 = 0.f, a1 = 0.f;
    const int j0 = st * (TSEQ / 4);
    for (int j = j0; j < j0 + TSEQ / 4; j += 2) {
        a0 += sc[j]     * Vb[(size_t)j       * DHEAD + dm];
        a1 += sc[j + 1] * Vb[(size_t)(j + 1) * DHEAD + dm];
    }
    part[st][dm] = a0 + a1;
    __syncthreads();
    if (tid < DHEAD) {
        float tot = part[0][tid] + part[1][tid] + part[2][tid] + part[3][tid];
        O[(size_t)bh * TSEQ * DHEAD + tid] = tot / L;
    }
}

extern "C" void kernel_launch(void* const* d_in, const int* in_sizes, int n_in,
                              void* d_out, int out_size) {
    const float* Q = (const float*)d_in[0];
    const float* K = (const float*)d_in[1];
    const float* V = (const float*)d_in[2];
    const float* M = (const float*)d_in[3];
    float* O = (float*)d_out;

    dim3 grid(NB, NBH);
    attn_block_kernel<<<grid, 256>>>(Q, K, V, M, O);
    attn_global_kernel<<<NBH, 256>>>(Q, K, V, M, O);
}

// round 3
// speedup vs baseline: 3.7762x; 3.7762x over previous
#include <cuda_runtime.h>
#include <cuda_bf16.h>
#include <cstdint>

#define TSEQ 4096
#define DH   64
#define BS   128
#define NB   32
#define NH   16
#define NBH  32

// ---------------- low-level helpers (sm_100 base ISA only) ----------------
__device__ __forceinline__ uint32_t smem_u32(const void* p) {
    uint32_t a;
    asm("{ .reg .u64 t; cvta.to.shared.u64 t, %1; cvt.u32.u64 %0, t; }"
        : "=r"(a) : "l"(p));
    return a;
}
__device__ __forceinline__ void mma_bf16(float* d, const uint32_t* a, const uint32_t* b) {
    asm volatile(
        "mma.sync.aligned.m16n8k16.row.col.f32.bf16.bf16.f32 "
        "{%0,%1,%2,%3}, {%4,%5,%6,%7}, {%8,%9}, {%0,%1,%2,%3};"
        : "+f"(d[0]), "+f"(d[1]), "+f"(d[2]), "+f"(d[3])
        : "r"(a[0]), "r"(a[1]), "r"(a[2]), "r"(a[3]), "r"(b[0]), "r"(b[1]));
}
__device__ __forceinline__ void ldsm_x2(uint32_t* r, uint32_t addr) {
    asm volatile("ldmatrix.sync.aligned.m8n8.x2.shared.b16 {%0,%1}, [%2];"
                 : "=r"(r[0]), "=r"(r[1]) : "r"(addr));
}
__device__ __forceinline__ void ldsm_x2_t(uint32_t* r, uint32_t addr) {
    asm volatile("ldmatrix.sync.aligned.m8n8.x2.trans.shared.b16 {%0,%1}, [%2];"
                 : "=r"(r[0]), "=r"(r[1]) : "r"(addr));
}
#define SW128(x) ((x) ^ (((x) >> 3) & 0x70))

// split fp32 pair -> (hi bf16x2, lo bf16x2)
__device__ __forceinline__ void pksp(float x, float y, uint32_t& h, uint32_t& l) {
    unsigned short hx = __bfloat16_as_ushort(__float2bfloat16(x));
    unsigned short hy = __bfloat16_as_ushort(__float2bfloat16(y));
    float fx = __bfloat162float(__ushort_as_bfloat16(hx));
    float fy = __bfloat162float(__ushort_as_bfloat16(hy));
    h = ((uint32_t)hy << 16) | hx;
    unsigned short lx = __bfloat16_as_ushort(__float2bfloat16(x - fx));
    unsigned short ly = __bfloat16_as_ushort(__float2bfloat16(y - fy));
    l = ((uint32_t)ly << 16) | lx;
}

// smem layout (dynamic)
static constexpr int OF_KH  = 0;              // 128x64 bf16 = 16 KB
static constexpr int OF_KL  = 16384;
static constexpr int OF_VH  = 32768;
static constexpr int OF_VL  = 49152;
static constexpr int OF_MSK = 65536;          // 128 f32
static constexpr int OF_K0  = OF_MSK + 512;   // 64 f32
static constexpr int OF_V0  = OF_K0 + 256;    // 64 f32
static constexpr int OF_EG  = OF_V0 + 256;    // 128 f32
static constexpr int SMEM_BYTES = OF_EG + 512;

// ==================== main block-local attention kernel ====================
__global__ __launch_bounds__(256, 1)
void attn_block_kernel(const float* __restrict__ Q, const float* __restrict__ K,
                       const float* __restrict__ V, const float* __restrict__ M,
                       float* __restrict__ O) {
    extern __shared__ __align__(128) char smem[];
    const uint32_t sb = smem_u32(smem);
    const int tid  = threadIdx.x;
    const int lane = tid & 31;
    const int warp = tid >> 5;
    const int b    = blockIdx.x;
    const int bh   = blockIdx.y;
    const int nIdx = bh / NH;

    const float* Qg = Q + ((size_t)bh * TSEQ + (size_t)b * BS) * DH;
    const float* Kg = K + (size_t)bh * TSEQ * DH;
    const float* Vg = V + (size_t)bh * TSEQ * DH;
    const float* Mr = M + (size_t)nIdx * TSEQ;
    float*       Og = O + ((size_t)bh * TSEQ + (size_t)b * BS) * DH;

    float* msk = (float*)(smem + OF_MSK);
    float* k0s = (float*)(smem + OF_K0);
    float* v0s = (float*)(smem + OF_V0);
    float* egs = (float*)(smem + OF_EG);

    if (tid < DH) { k0s[tid] = Kg[tid]; v0s[tid] = Vg[tid]; }

    // ---- Q fragments (hi/lo), resident across all key blocks ----
    const int r0 = warp * 16;
    uint32_t qh[4][4], ql[4][4];
    #pragma unroll
    for (int ks = 0; ks < 4; ks++)
        #pragma unroll
        for (int i = 0; i < 4; i++) {
            const int rr = r0 + (lane >> 2) + (i & 1) * 8;
            const int cc = ks * 16 + (lane & 3) * 2 + (i >> 1) * 8;
            float2 v = *(const float2*)(Qg + rr * DH + cc);
            pksp(v.x, v.y, qh[ks][i], ql[ks][i]);
        }
    __syncthreads();

    // ---- global-token seed e_g[r] = exp(0.125 * q_r . k0) ----
    {
        const int rr = r0 + (lane >> 1);
        const int hf = lane & 1;
        const float* qr = Qg + (size_t)rr * DH + hf * 32;
        float p = 0.f;
        #pragma unroll
        for (int i = 0; i < 32; i++) p += qr[i] * k0s[hf * 32 + i];
        p += __shfl_xor_sync(0xffffffffu, p, 1);
        if (hf == 0) egs[rr] = __expf(p * 0.125f);
    }
    __syncwarp();

    float o[8][4];
    #pragma unroll
    for (int i = 0; i < 8; i++)
        #pragma unroll
        for (int j = 0; j < 4; j++) o[i][j] = 0.f;
    float lr0 = 0.f, lr8 = 0.f;

    for (int kb = b - 1; kb <= b + 1; kb++) {
        if (kb < 0 || kb >= NB) continue;
        const int kb0 = kb * BS;

        __syncthreads();   // previous tile fully consumed
        {
            const float4* kp = (const float4*)(Kg + (size_t)kb0 * DH);
            const float4* vp = (const float4*)(Vg + (size_t)kb0 * DH);
            #pragma unroll
            for (int f = tid; f < 2048; f += 256) {
                const uint32_t sw = SW128((uint32_t)(f * 8));
                uint32_t h0, l0, h1, l1;
                float4 kv = kp[f];
                pksp(kv.x, kv.y, h0, l0); pksp(kv.z, kv.w, h1, l1);
                *(uint2*)(smem + OF_KH + sw) = make_uint2(h0, h1);
                *(uint2*)(smem + OF_KL + sw) = make_uint2(l0, l1);
                float4 vv = vp[f];
                pksp(vv.x, vv.y, h0, l0); pksp(vv.z, vv.w, h1, l1);
                *(uint2*)(smem + OF_VH + sw) = make_uint2(h0, h1);
                *(uint2*)(smem + OF_VL + sw) = make_uint2(l0, l1);
            }
            if (tid < BS) msk[tid] = Mr[kb0 + tid];
        }
        __syncthreads();

        #pragma unroll
        for (int h = 0; h < 2; h++) {      // two 64-key halves
            // ---- S = Q K^T (3-term split), 8 n-tiles of 8 keys ----
            float s[8][4];
            #pragma unroll
            for (int i = 0; i < 8; i++)
                #pragma unroll
                for (int j = 0; j < 4; j++) s[i][j] = 0.f;

            #pragma unroll
            for (int nt = 0; nt < 8; nt++) {
                const int keyrow = h * 64 + nt * 8 + (lane & 7);
                #pragma unroll
                for (int ks = 0; ks < 4; ks++) {
                    const uint32_t off =
                        (uint32_t)(keyrow * 128 + ks * 32 + ((lane >> 3) & 1) * 16);
                    const uint32_t swo = SW128(off);
                    uint32_t bhh[2], bll[2];
                    ldsm_x2(bhh, sb + OF_KH + swo);
                    ldsm_x2(bll, sb + OF_KL + swo);
                    mma_bf16(s[nt], qh[ks], bhh);
                    mma_bf16(s[nt], qh[ks], bll);
                    mma_bf16(s[nt], ql[ks], bhh);
                }
            }

            // ---- softmax (no-max) -> P fragments -> PV ----
            #pragma unroll
            for (int kt = 0; kt < 4; kt++) {
                float e[2][4];
                #pragma unroll
                for (int u = 0; u < 2; u++) {
                    const int nt = 2 * kt + u;
                    #pragma unroll
                    for (int j = 0; j < 4; j++) {
                        const int col = h * 64 + nt * 8 + (lane & 3) * 2 + (j & 1);
                        float ev = __expf(fmaf(s[nt][j], 0.125f, msk[col]));
                        if (kb0 + col == 0) ev = 0.f;   // window never sees pos 0
                        e[u][j] = ev;
                        if (j < 2) lr0 += ev; else lr8 += ev;
                    }
                }
                uint32_t ph[4], pl[4];
                pksp(e[0][0], e[0][1], ph[0], pl[0]);
                pksp(e[0][2], e[0][3], ph[1], pl[1]);
                pksp(e[1][0], e[1][1], ph[2], pl[2]);
                pksp(e[1][2], e[1][3], ph[3], pl[3]);

                const int vrow = h * 64 + kt * 16 + (lane & 15);
                #pragma unroll
                for (int n2 = 0; n2 < 8; n2++) {
                    const uint32_t off = (uint32_t)(vrow * 128 + n2 * 16);
                    const uint32_t swo = SW128(off);
                    uint32_t bhh[2], bll[2];
                    ldsm_x2_t(bhh, sb + OF_VH + swo);
                    ldsm_x2_t(bll, sb + OF_VL + swo);
                    mma_bf16(o[n2], ph, bhh);
                    mma_bf16(o[n2], ph, bll);
                    mma_bf16(o[n2], pl, bhh);
                }
            }
        }
    }

    // ---- epilogue: add global token, normalize, store ----
    lr0 += __shfl_xor_sync(0xffffffffu, lr0, 1);
    lr0 += __shfl_xor_sync(0xffffffffu, lr0, 2);
    lr8 += __shfl_xor_sync(0xffffffffu, lr8, 1);
    lr8 += __shfl_xor_sync(0xffffffffu, lr8, 2);
    const int r = lane >> 2;
    const float eg0 = egs[r0 + r];
    const float eg8 = egs[r0 + r + 8];
    const float il0 = 1.f / (lr0 + eg0);
    const float il8 = 1.f / (lr8 + eg8);
    #pragma unroll
    for (int n2 = 0; n2 < 8; n2++) {
        const int d = n2 * 8 + (lane & 3) * 2;
        float2 w0 = make_float2((o[n2][0] + eg0 * v0s[d])     * il0,
                                (o[n2][1] + eg0 * v0s[d + 1]) * il0);
        float2 w8 = make_float2((o[n2][2] + eg8 * v0s[d])     * il8,
                                (o[n2][3] + eg8 * v0s[d + 1]) * il8);
        *(float2*)(Og + (size_t)(r0 + r)     * DH + d) = w0;
        *(float2*)(Og + (size_t)(r0 + r + 8) * DH + d) = w8;
    }
}

// ============== row-0 full attention (split-K partials + reduce) ==========
__device__ float g_part[NBH][8][DH];
__device__ float g_plsum[NBH][8];

__global__ __launch_bounds__(256)
void row0_partial_kernel(const float* __restrict__ Q, const float* __restrict__ K,
                         const float* __restrict__ V, const float* __restrict__ M) {
    const int st = blockIdx.x;     // stripe of 512 keys
    const int bh = blockIdx.y;
    const int nIdx = bh / NH;
    const int tid = threadIdx.x;
    const int j0 = st * 512;

    __shared__ float q0[DH];
    __shared__ float esm[512];
    __shared__ float red[256];
    __shared__ float part[4][DH];

    const float* Qg = Q + (size_t)bh * TSEQ * DH;
    const float* Kg = K + (size_t)bh * TSEQ * DH;
    const float* Vg = V + (size_t)bh * TSEQ * DH;
    const float* Mr = M + (size_t)nIdx * TSEQ;

    if (tid < DH) q0[tid] = Qg[tid];
    __syncthreads();

    float l = 0.f;
    for (int j = tid; j < 512; j += 256) {
        const int pos = j0 + j;
        float dot = 0.f;
        const float4* kp = (const float4*)(Kg + (size_t)pos * DH);
        #pragma unroll
        for (int i = 0; i < 16; i++) {
            float4 kv = kp[i];
            dot += q0[4*i]*kv.x + q0[4*i+1]*kv.y + q0[4*i+2]*kv.z + q0[4*i+3]*kv.w;
        }
        float e = __expf(fmaf(dot, 0.125f, Mr[pos]));
        esm[j] = e;
        l += e;
    }
    red[tid] = l; __syncthreads();
    for (int s = 128; s > 0; s >>= 1) {
        if (tid < s) red[tid] += red[tid + s];
        __syncthreads();
    }
    if (tid == 0) g_plsum[bh][st] = red[0];

    const int dm = tid & 63, q = tid >> 6;
    float a = 0.f;
    for (int k = q * 128; k < q * 128 + 128; k++)
        a += esm[k] * Vg[(size_t)(j0 + k) * DH + dm];
    part[q][dm] = a;
    __syncthreads();
    if (tid < DH)
        g_part[bh][st][tid] = part[0][tid] + part[1][tid] + part[2][tid] + part[3][tid];
}

__global__ void row0_reduce_kernel(float* __restrict__ O) {
    const int bh = blockIdx.x;
    const int d = threadIdx.x;
    float s = 0.f, l = 0.f;
    #pragma unroll
    for (int st = 0; st < 8; st++) { s += g_part[bh][st][d]; l += g_plsum[bh][st]; }
    O[(size_t)bh * TSEQ * DH + d] = s / l;
}

// ================================ launch ===================================
extern "C" void kernel_launch(void* const* d_in, const int* in_sizes, int n_in,
                              void* d_out, int out_size) {
    const float* Q = (const float*)d_in[0];
    const float* K = (const float*)d_in[1];
    const float* V = (const float*)d_in[2];
    const float* M = (const float*)d_in[3];
    float* O = (float*)d_out;

    cudaFuncSetAttribute(attn_block_kernel,
                         cudaFuncAttributeMaxDynamicSharedMemorySize, SMEM_BYTES);
    dim3 grid(NB, NBH);
    attn_block_kernel<<<grid, 256, SMEM_BYTES>>>(Q, K, V, M, O);
    dim3 gridp(8, NBH);
    row0_partial_kernel<<<gridp, 256>>>(Q, K, V, M);
    row0_reduce_kernel<<<NBH, DH>>>(O);
}

// round 5
// speedup vs baseline: 4.0408x; 1.0701x over previous
#include <cuda_runtime.h>
#include <cuda_bf16.h>
#include <cstdint>

#define TSEQ 4096
#define DH   64
#define BS   128
#define NB   32
#define NH   16
#define NBH  32

// ---------------- low-level helpers (sm_100 base ISA only) ----------------
__device__ __forceinline__ uint32_t smem_u32(const void* p) {
    uint32_t a;
    asm("{ .reg .u64 t; cvta.to.shared.u64 t, %1; cvt.u32.u64 %0, t; }"
        : "=r"(a) : "l"(p));
    return a;
}
__device__ __forceinline__ void mma_bf16(float* d, const uint32_t* a, const uint32_t* b) {
    asm volatile(
        "mma.sync.aligned.m16n8k16.row.col.f32.bf16.bf16.f32 "
        "{%0,%1,%2,%3}, {%4,%5,%6,%7}, {%8,%9}, {%0,%1,%2,%3};"
        : "+f"(d[0]), "+f"(d[1]), "+f"(d[2]), "+f"(d[3])
        : "r"(a[0]), "r"(a[1]), "r"(a[2]), "r"(a[3]), "r"(b[0]), "r"(b[1]));
}
__device__ __forceinline__ void ldsm_x4(uint32_t* r, uint32_t addr) {
    asm volatile("ldmatrix.sync.aligned.m8n8.x4.shared.b16 {%0,%1,%2,%3}, [%4];"
                 : "=r"(r[0]), "=r"(r[1]), "=r"(r[2]), "=r"(r[3]) : "r"(addr));
}
__device__ __forceinline__ void ldsm_x4_t(uint32_t* r, uint32_t addr) {
    asm volatile("ldmatrix.sync.aligned.m8n8.x4.trans.shared.b16 {%0,%1,%2,%3}, [%4];"
                 : "=r"(r[0]), "=r"(r[1]), "=r"(r[2]), "=r"(r[3]) : "r"(addr));
}
#define SW128(x) ((x) ^ (((x) >> 3) & 0x70))

// split fp32 pair -> (hi bf16x2, lo bf16x2)
__device__ __forceinline__ void pksp(float x, float y, uint32_t& h, uint32_t& l) {
    unsigned short hx = __bfloat16_as_ushort(__float2bfloat16(x));
    unsigned short hy = __bfloat16_as_ushort(__float2bfloat16(y));
    float fx = __bfloat162float(__ushort_as_bfloat16(hx));
    float fy = __bfloat162float(__ushort_as_bfloat16(hy));
    h = ((uint32_t)hy << 16) | hx;
    unsigned short lx = __bfloat16_as_ushort(__float2bfloat16(x - fx));
    unsigned short ly = __bfloat16_as_ushort(__float2bfloat16(y - fy));
    l = ((uint32_t)ly << 16) | lx;
}

// smem layout (dynamic)
static constexpr int OF_KH  = 0;              // 128x64 bf16 = 16 KB
static constexpr int OF_KL  = 16384;
static constexpr int OF_VH  = 32768;
static constexpr int OF_VL  = 49152;
static constexpr int OF_MSK = 65536;          // 128 f32
static constexpr int OF_K0  = OF_MSK + 512;   // 64 f32
static constexpr int OF_V0  = OF_K0 + 256;    // 64 f32
static constexpr int OF_EG  = OF_V0 + 256;    // 128 f32
static constexpr int SMEM_BYTES = OF_EG + 512;

// ==================== main block-local attention kernel ====================
__global__ __launch_bounds__(256, 1)
void attn_block_kernel(const float* __restrict__ Q, const float* __restrict__ K,
                       const float* __restrict__ V, const float* __restrict__ M,
                       float* __restrict__ O) {
    extern __shared__ __align__(128) char smem[];
    const uint32_t sb = smem_u32(smem);
    const int tid  = threadIdx.x;
    const int lane = tid & 31;
    const int warp = tid >> 5;
    const int b    = blockIdx.x;
    const int bh   = blockIdx.y;
    const int nIdx = bh / NH;

    const float* Qg = Q + ((size_t)bh * TSEQ + (size_t)b * BS) * DH;
    const float* Kg = K + (size_t)bh * TSEQ * DH;
    const float* Vg = V + (size_t)bh * TSEQ * DH;
    const float* Mr = M + (size_t)nIdx * TSEQ;
    float*       Og = O + ((size_t)bh * TSEQ + (size_t)b * BS) * DH;

    float* msk = (float*)(smem + OF_MSK);
    float* k0s = (float*)(smem + OF_K0);
    float* v0s = (float*)(smem + OF_V0);
    float* egs = (float*)(smem + OF_EG);

    if (tid < DH) { k0s[tid] = Kg[tid]; v0s[tid] = Vg[tid]; }

    // ---- Q fragments (hi/lo), resident across all key blocks ----
    const int r0 = warp * 16;
    uint32_t qh[4][4], ql[4][4];
    #pragma unroll
    for (int ks = 0; ks < 4; ks++)
        #pragma unroll
        for (int i = 0; i < 4; i++) {
            const int rr = r0 + (lane >> 2) + (i & 1) * 8;
            const int cc = ks * 16 + (lane & 3) * 2 + (i >> 1) * 8;
            float2 v = *(const float2*)(Qg + rr * DH + cc);
            pksp(v.x, v.y, qh[ks][i], ql[ks][i]);
        }
    __syncthreads();

    // ---- global-token seed e_g[r] = exp(0.125 * q_r . k0) ----
    {
        const int rr = r0 + (lane >> 1);
        const int hf = lane & 1;
        const float* qr = Qg + (size_t)rr * DH + hf * 32;
        float p = 0.f;
        #pragma unroll
        for (int i = 0; i < 32; i++) p += qr[i] * k0s[hf * 32 + i];
        p += __shfl_xor_sync(0xffffffffu, p, 1);
        if (hf == 0) egs[rr] = __expf(p * 0.125f);
    }
    __syncwarp();

    float o[8][4];
    #pragma unroll
    for (int i = 0; i < 8; i++)
        #pragma unroll
        for (int j = 0; j < 4; j++) o[i][j] = 0.f;
    float lr0 = 0.f, lr8 = 0.f;

    // x4 ldmatrix per-lane address components (constant across loop)
    const int k_rowoff = ((lane >> 4) << 3) + (lane & 7);     // key row within 16-pair
    const int k_coloff = ((lane >> 3) & 1) * 16;              // byte col within 32
    const int v_rowoff = (lane & 15);
    const int v_coloff = (lane >> 4) * 16;

    for (int kb = b - 1; kb <= b + 1; kb++) {
        if (kb < 0 || kb >= NB) continue;
        const int kb0 = kb * BS;

        __syncthreads();   // previous tile fully consumed
        {
            const float4* kp = (const float4*)(Kg + (size_t)kb0 * DH);
            const float4* vp = (const float4*)(Vg + (size_t)kb0 * DH);
            #pragma unroll
            for (int f = tid; f < 2048; f += 256) {
                const uint32_t sw = SW128((uint32_t)(f * 8));
                uint32_t h0, l0, h1, l1;
                float4 kv = kp[f];
                pksp(kv.x, kv.y, h0, l0); pksp(kv.z, kv.w, h1, l1);
                *(uint2*)(smem + OF_KH + sw) = make_uint2(h0, h1);
                *(uint2*)(smem + OF_KL + sw) = make_uint2(l0, l1);
                float4 vv = vp[f];
                pksp(vv.x, vv.y, h0, l0); pksp(vv.z, vv.w, h1, l1);
                *(uint2*)(smem + OF_VH + sw) = make_uint2(h0, h1);
                *(uint2*)(smem + OF_VL + sw) = make_uint2(l0, l1);
            }
            if (tid < BS) msk[tid] = Mr[kb0 + tid];
        }
        __syncthreads();

        #pragma unroll
        for (int h = 0; h < 2; h++) {      // two 64-key halves
            // ---- S = Q K^T (3-term split), term-major MMA issue ----
            float s[8][4];
            #pragma unroll
            for (int i = 0; i < 8; i++)
                #pragma unroll
                for (int j = 0; j < 4; j++) s[i][j] = 0.f;

            #pragma unroll
            for (int ks = 0; ks < 4; ks++) {
                uint32_t BH[8][2], BL[8][2];
                #pragma unroll
                for (int np = 0; np < 4; np++) {     // nt pair
                    const int keyrow = h * 64 + np * 16 + k_rowoff;
                    const uint32_t off = (uint32_t)(keyrow * 128 + ks * 32 + k_coloff);
                    const uint32_t swo = SW128(off);
                    uint32_t r[4];
                    ldsm_x4(r, sb + OF_KH + swo);
                    BH[2*np][0] = r[0]; BH[2*np][1] = r[1];
                    BH[2*np+1][0] = r[2]; BH[2*np+1][1] = r[3];
                    ldsm_x4(r, sb + OF_KL + swo);
                    BL[2*np][0] = r[0]; BL[2*np][1] = r[1];
                    BL[2*np+1][0] = r[2]; BL[2*np+1][1] = r[3];
                }
                #pragma unroll
                for (int nt = 0; nt < 8; nt++) mma_bf16(s[nt], qh[ks], BH[nt]);
                #pragma unroll
                for (int nt = 0; nt < 8; nt++) mma_bf16(s[nt], qh[ks], BL[nt]);
                #pragma unroll
                for (int nt = 0; nt < 8; nt++) mma_bf16(s[nt], ql[ks], BH[nt]);
            }

            // ---- softmax (no-max) -> P fragments -> PV (term-major) ----
            #pragma unroll
            for (int kt = 0; kt < 4; kt++) {
                // V fragments first (hide LDSM latency behind exp math)
                uint32_t VH[8][2], VL[8][2];
                #pragma unroll
                for (int np = 0; np < 4; np++) {     // n2 pair
                    const int vrow = h * 64 + kt * 16 + v_rowoff;
                    const uint32_t off = (uint32_t)(vrow * 128 + np * 32 + v_coloff);
                    const uint32_t swo = SW128(off);
                    uint32_t r[4];
                    ldsm_x4_t(r, sb + OF_VH + swo);
                    VH[2*np][0] = r[0]; VH[2*np][1] = r[1];
                    VH[2*np+1][0] = r[2]; VH[2*np+1][1] = r[3];
                    ldsm_x4_t(r, sb + OF_VL + swo);
                    VL[2*np][0] = r[0]; VL[2*np][1] = r[1];
                    VL[2*np+1][0] = r[2]; VL[2*np+1][1] = r[3];
                }

                float e[2][4];
                #pragma unroll
                for (int u = 0; u < 2; u++) {
                    const int nt = 2 * kt + u;
                    #pragma unroll
                    for (int j = 0; j < 4; j++) {
                        const int col = h * 64 + nt * 8 + (lane & 3) * 2 + (j & 1);
                        float ev = __expf(fmaf(s[nt][j], 0.125f, msk[col]));
                        if (kb0 + col == 0) ev = 0.f;   // window never sees pos 0
                        e[u][j] = ev;
                        if (j < 2) lr0 += ev; else lr8 += ev;
                    }
                }
                uint32_t ph[4], pl[4];
                pksp(e[0][0], e[0][1], ph[0], pl[0]);
                pksp(e[0][2], e[0][3], ph[1], pl[1]);
                pksp(e[1][0], e[1][1], ph[2], pl[2]);
                pksp(e[1][2], e[1][3], ph[3], pl[3]);

                #pragma unroll
                for (int n2 = 0; n2 < 8; n2++) mma_bf16(o[n2], ph, VH[n2]);
                #pragma unroll
                for (int n2 = 0; n2 < 8; n2++) mma_bf16(o[n2], ph, VL[n2]);
                #pragma unroll
                for (int n2 = 0; n2 < 8; n2++) mma_bf16(o[n2], pl, VH[n2]);
            }
        }
    }

    // ---- epilogue: add global token, normalize, store ----
    lr0 += __shfl_xor_sync(0xffffffffu, lr0, 1);
    lr0 += __shfl_xor_sync(0xffffffffu, lr0, 2);
    lr8 += __shfl_xor_sync(0xffffffffu, lr8, 1);
    lr8 += __shfl_xor_sync(0xffffffffu, lr8, 2);
    const int r = lane >> 2;
    const float eg0 = egs[r0 + r];
    const float eg8 = egs[r0 + r + 8];
    const float il0 = 1.f / (lr0 + eg0);
    const float il8 = 1.f / (lr8 + eg8);
    #pragma unroll
    for (int n2 = 0; n2 < 8; n2++) {
        const int d = n2 * 8 + (lane & 3) * 2;
        float2 w0 = make_float2((o[n2][0] + eg0 * v0s[d])     * il0,
                                (o[n2][1] + eg0 * v0s[d + 1]) * il0);
        float2 w8 = make_float2((o[n2][2] + eg8 * v0s[d])     * il8,
                                (o[n2][3] + eg8 * v0s[d + 1]) * il8);
        *(float2*)(Og + (size_t)(r0 + r)     * DH + d) = w0;
        *(float2*)(Og + (size_t)(r0 + r + 8) * DH + d) = w8;
    }
}

// ============== row-0 full attention (split-K partials + reduce) ==========
__device__ float g_part[NBH][8][DH];
__device__ float g_plsum[NBH][8];

__global__ __launch_bounds__(256)
void row0_partial_kernel(const float* __restrict__ Q, const float* __restrict__ K,
                         const float* __restrict__ V, const float* __restrict__ M) {
    const int st = blockIdx.x;     // stripe of 512 keys
    const int bh = blockIdx.y;
    const int nIdx = bh / NH;
    const int tid = threadIdx.x;
    const int j0 = st * 512;

    __shared__ float q0[DH];
    __shared__ float esm[512];
    __shared__ float red[256];
    __shared__ float part[4][DH];

    const float* Qg = Q + (size_t)bh * TSEQ * DH;
    const float* Kg = K + (size_t)bh * TSEQ * DH;
    const float* Vg = V + (size_t)bh * TSEQ * DH;
    const float* Mr = M + (size_t)nIdx * TSEQ;

    if (tid < DH) q0[tid] = Qg[tid];
    __syncthreads();

    float l = 0.f;
    for (int j = tid; j < 512; j += 256) {
        const int pos = j0 + j;
        float dot = 0.f;
        const float4* kp = (const float4*)(Kg + (size_t)pos * DH);
        #pragma unroll
        for (int i = 0; i < 16; i++) {
            float4 kv = kp[i];
            dot += q0[4*i]*kv.x + q0[4*i+1]*kv.y + q0[4*i+2]*kv.z + q0[4*i+3]*kv.w;
        }
        float e = __expf(fmaf(dot, 0.125f, Mr[pos]));
        esm[j] = e;
        l += e;
    }
    red[tid] = l; __syncthreads();
    for (int s = 128; s > 0; s >>= 1) {
        if (tid < s) red[tid] += red[tid + s];
        __syncthreads();
    }
    if (tid == 0) g_plsum[bh][st] = red[0];

    const int dm = tid & 63, q = tid >> 6;
    float a = 0.f;
    for (int k = q * 128; k < q * 128 + 128; k++)
        a += esm[k] * Vg[(size_t)(j0 + k) * DH + dm];
    part[q][dm] = a;
    __syncthreads();
    if (tid < DH)
        g_part[bh][st][tid] = part[0][tid] + part[1][tid] + part[2][tid] + part[3][tid];
}

__global__ void row0_reduce_kernel(float* __restrict__ O) {
    const int bh = blockIdx.x;
    const int d = threadIdx.x;
    float s = 0.f, l = 0.f;
    #pragma unroll
    for (int st = 0; st < 8; st++) { s += g_part[bh][st][d]; l += g_plsum[bh][st]; }
    O[(size_t)bh * TSEQ * DH + d] = s / l;
}

// ================================ launch ===================================
extern "C" void kernel_launch(void* const* d_in, const int* in_sizes, int n_in,
                              void* d_out, int out_size) {
    const float* Q = (const float*)d_in[0];
    const float* K = (const float*)d_in[1];
    const float* V = (const float*)d_in[2];
    const float* M = (const float*)d_in[3];
    float* O = (float*)d_out;

    cudaFuncSetAttribute(attn_block_kernel,
                         cudaFuncAttributeMaxDynamicSharedMemorySize, SMEM_BYTES);
    dim3 grid(NB, NBH);
    attn_block_kernel<<<grid, 256, SMEM_BYTES>>>(Q, K, V, M, O);
    dim3 gridp(8, NBH);
    row0_partial_kernel<<<gridp, 256>>>(Q, K, V, M);
    row0_reduce_kernel<<<NBH, DH>>>(O);
}